// round 1
// baseline (speedup 1.0000x reference)
#include <cuda_runtime.h>
#include <math.h>

#define B_  16
#define N_  1024
#define D_  768
#define H_  12
#define HD_ 64
#define M_  (B_ * N_)   // 16384

// Scratch buffers (device globals -- no allocation in kernel_launch)
__device__ float g_q[B_ * H_ * N_ * HD_];
__device__ float g_k[B_ * H_ * N_ * HD_];
__device__ float g_v[B_ * H_ * N_ * HD_];
__device__ float g_ao[M_ * D_];

// ---------------------------------------------------------------------------
// GEMM: C = X @ W + bias
//   X: [M_, D_] row-major, W: [D_, D_] row-major
//   MODE 0: out[m*D_ + n]                       (plain row-major)
//   MODE 1: out[((b*H_+h)*N_ + r)*HD_ + d]      (scatter to [B,H,N,hd])
// Tiles: 128x128x8, 256 threads, 8x8 per-thread microkernel.
// ---------------------------------------------------------------------------
template <int MODE>
__global__ __launch_bounds__(256)
void gemm_kernel(const float* __restrict__ X, const float* __restrict__ W,
                 const float* __restrict__ bias, float* __restrict__ out)
{
    __shared__ float As[8 * 132];   // transposed A tile, padded stride 132
    __shared__ float Bs[8 * 128];

    const int tid = threadIdx.x;
    const int m0 = blockIdx.y * 128;
    const int n0 = blockIdx.x * 128;
    const int tx = tid & 15;
    const int ty = tid >> 4;

    // A loads: each thread loads one float4 along K (rows of X)
    const int a_row = tid >> 1;            // 0..127
    const int a_col = (tid & 1) * 4;       // 0 or 4
    // B loads: each thread loads one float4 along N
    const int b_row = tid >> 5;            // 0..7
    const int b_col = (tid & 31) * 4;      // 0..124

    const float* Xp = X + (size_t)(m0 + a_row) * D_ + a_col;
    const float* Wp = W + (size_t)b_row * D_ + n0 + b_col;

    float acc[8][8];
#pragma unroll
    for (int i = 0; i < 8; i++)
#pragma unroll
        for (int j = 0; j < 8; j++) acc[i][j] = 0.f;

    for (int k0 = 0; k0 < D_; k0 += 8) {
        float4 av = *(const float4*)(Xp + k0);
        float4 bv = *(const float4*)(Wp + (size_t)k0 * D_);

        As[(a_col + 0) * 132 + a_row] = av.x;
        As[(a_col + 1) * 132 + a_row] = av.y;
        As[(a_col + 2) * 132 + a_row] = av.z;
        As[(a_col + 3) * 132 + a_row] = av.w;
        *(float4*)(&Bs[b_row * 128 + b_col]) = bv;
        __syncthreads();

#pragma unroll
        for (int k = 0; k < 8; k++) {
            float4 a0 = *(const float4*)(&As[k * 132 + ty * 8]);
            float4 a1 = *(const float4*)(&As[k * 132 + ty * 8 + 4]);
            float4 b0 = *(const float4*)(&Bs[k * 128 + tx * 8]);
            float4 b1 = *(const float4*)(&Bs[k * 128 + tx * 8 + 4]);
            float ar[8] = {a0.x, a0.y, a0.z, a0.w, a1.x, a1.y, a1.z, a1.w};
            float br[8] = {b0.x, b0.y, b0.z, b0.w, b1.x, b1.y, b1.z, b1.w};
#pragma unroll
            for (int i = 0; i < 8; i++)
#pragma unroll
                for (int j = 0; j < 8; j++)
                    acc[i][j] = fmaf(ar[i], br[j], acc[i][j]);
        }
        __syncthreads();
    }

    // Epilogue
#pragma unroll
    for (int i = 0; i < 8; i++) {
        const int m = m0 + ty * 8 + i;
#pragma unroll
        for (int j = 0; j < 8; j++) {
            const int n = n0 + tx * 8 + j;
            const float v = acc[i][j] + bias[n];
            if (MODE == 0) {
                out[(size_t)m * D_ + n] = v;
            } else {
                const int h = n >> 6;
                const int d = n & 63;
                const int b = m >> 10;
                const int r = m & 1023;
                out[(((size_t)b * H_ + h) * N_ + r) * HD_ + d] = v;
            }
        }
    }
}

// ---------------------------------------------------------------------------
// Fused attention: per (b, h, 64-row q tile). Online softmax (flash-style).
// Q,K,V in [B,H,N,hd]; output scattered into [M_, D_] (row b*N+q, col h*64+d).
// 256 threads: thread (ty,tx) owns 4 q-rows x 4 cols.
// ---------------------------------------------------------------------------
#define QS_STRIDE 65
#define KP_STRIDE 68   // Ps uses stride 68; Ks uses stride 65 inside same buf
#define VS_STRIDE 68
#define ATTN_SMEM ((64 * QS_STRIDE + 64 * KP_STRIDE + 64 * VS_STRIDE) * 4)

__global__ __launch_bounds__(256)
void attn_kernel(const float* __restrict__ Q, const float* __restrict__ K,
                 const float* __restrict__ V, float* __restrict__ O)
{
    extern __shared__ float sm[];
    float* Qs = sm;                       // 64 x (stride 65)
    float* KP = sm + 64 * QS_STRIDE;      // K tile (stride 65) then P tile (stride 68)
    float* Vs = KP + 64 * KP_STRIDE;      // 64 x (stride 68)

    const int tid = threadIdx.x;
    const int tx = tid & 15;
    const int ty = tid >> 4;
    const int b  = blockIdx.z;
    const int h  = blockIdx.y;
    const int q0 = blockIdx.x * 64;

    const float* Qb = Q + (((size_t)b * H_ + h) * N_ + q0) * HD_;
    const float* Kb = K + (((size_t)b * H_ + h) * N_) * HD_;
    const float* Vb = V + (((size_t)b * H_ + h) * N_) * HD_;

    // Load Q tile
    for (int idx = tid; idx < 64 * 64; idx += 256) {
        const int r = idx >> 6, c = idx & 63;
        Qs[r * QS_STRIDE + c] = Qb[idx];
    }

    float acc[4][4];
    float myM[4], myL[4];
#pragma unroll
    for (int i = 0; i < 4; i++) {
        myM[i] = -1e30f;
        myL[i] = 0.f;
#pragma unroll
        for (int j = 0; j < 4; j++) acc[i][j] = 0.f;
    }

    const float scale = 0.03608439182435161f;  // 1/sqrt(768)

    for (int t = 0; t < N_ / 64; ++t) {
        __syncthreads();  // prior PV reads of KP/Vs done (and Q load on t=0)

        const float* Kt = Kb + (size_t)t * 64 * HD_;
        const float* Vt = Vb + (size_t)t * 64 * HD_;
        for (int idx = tid; idx < 64 * 64; idx += 256) {
            const int r = idx >> 6, c = idx & 63;
            KP[r * QS_STRIDE + c] = Kt[idx];   // K tile at stride 65
            Vs[r * VS_STRIDE + c] = Vt[idx];
        }
        __syncthreads();

        // S = Q K^T (this thread's 4x4)
        float s[4][4];
#pragma unroll
        for (int i = 0; i < 4; i++)
#pragma unroll
            for (int j = 0; j < 4; j++) s[i][j] = 0.f;

#pragma unroll 8
        for (int k = 0; k < 64; ++k) {
            float a[4], bb[4];
#pragma unroll
            for (int i = 0; i < 4; i++) a[i] = Qs[(ty * 4 + i) * QS_STRIDE + k];
#pragma unroll
            for (int j = 0; j < 4; j++) bb[j] = KP[(tx * 4 + j) * QS_STRIDE + k];
#pragma unroll
            for (int i = 0; i < 4; i++)
#pragma unroll
                for (int j = 0; j < 4; j++)
                    s[i][j] = fmaf(a[i], bb[j], s[i][j]);
        }

        // Online softmax update (per q-row; 16-lane butterfly within tx group)
        float corr[4];
#pragma unroll
        for (int i = 0; i < 4; i++) {
            float tm = -1e30f;
#pragma unroll
            for (int j = 0; j < 4; j++) {
                s[i][j] *= scale;
                tm = fmaxf(tm, s[i][j]);
            }
#pragma unroll
            for (int o = 1; o < 16; o <<= 1)
                tm = fmaxf(tm, __shfl_xor_sync(0xffffffffu, tm, o));
            const float mn = fmaxf(myM[i], tm);
            corr[i] = __expf(myM[i] - mn);
            float rs = 0.f;
#pragma unroll
            for (int j = 0; j < 4; j++) {
                s[i][j] = __expf(s[i][j] - mn);
                rs += s[i][j];
            }
#pragma unroll
            for (int o = 1; o < 16; o <<= 1)
                rs += __shfl_xor_sync(0xffffffffu, rs, o);
            myL[i] = myL[i] * corr[i] + rs;
            myM[i] = mn;
#pragma unroll
            for (int j = 0; j < 4; j++) acc[i][j] *= corr[i];
        }

        __syncthreads();  // everyone done reading K tile before P overwrites it

        // Write P tile (stride 68)
#pragma unroll
        for (int i = 0; i < 4; i++)
#pragma unroll
            for (int j = 0; j < 4; j++)
                KP[(ty * 4 + i) * KP_STRIDE + tx * 4 + j] = s[i][j];
        __syncthreads();

        // O += P @ V
#pragma unroll 8
        for (int j = 0; j < 64; ++j) {
            float p[4];
#pragma unroll
            for (int i = 0; i < 4; i++) p[i] = KP[(ty * 4 + i) * KP_STRIDE + j];
            const float4 v4 = *(const float4*)(&Vs[j * VS_STRIDE + tx * 4]);
#pragma unroll
            for (int i = 0; i < 4; i++) {
                acc[i][0] = fmaf(p[i], v4.x, acc[i][0]);
                acc[i][1] = fmaf(p[i], v4.y, acc[i][1]);
                acc[i][2] = fmaf(p[i], v4.z, acc[i][2]);
                acc[i][3] = fmaf(p[i], v4.w, acc[i][3]);
            }
        }
    }

    // Normalize and write to [M_, D_] scratch (row b*N+q, col h*64+d)
    float* Op = O + ((size_t)b * N_ + q0) * D_ + h * HD_;
#pragma unroll
    for (int i = 0; i < 4; i++) {
        const float invl = 1.f / myL[i];
#pragma unroll
        for (int j = 0; j < 4; j++)
            Op[(size_t)(ty * 4 + i) * D_ + tx * 4 + j] = acc[i][j] * invl;
    }
}

// ---------------------------------------------------------------------------
extern "C" void kernel_launch(void* const* d_in, const int* in_sizes, int n_in,
                              void* d_out, int out_size)
{
    const float* X  = (const float*)d_in[0];
    const float* Wq = (const float*)d_in[1];
    const float* bq = (const float*)d_in[2];
    const float* Wk = (const float*)d_in[3];
    const float* bk = (const float*)d_in[4];
    const float* Wv = (const float*)d_in[5];
    const float* bv = (const float*)d_in[6];
    const float* Wo = (const float*)d_in[7];
    const float* bo = (const float*)d_in[8];
    float* out = (float*)d_out;

    float *qp, *kp, *vp, *aop;
    cudaGetSymbolAddress((void**)&qp,  g_q);
    cudaGetSymbolAddress((void**)&kp,  g_k);
    cudaGetSymbolAddress((void**)&vp,  g_v);
    cudaGetSymbolAddress((void**)&aop, g_ao);

    cudaFuncSetAttribute(attn_kernel,
                         cudaFuncAttributeMaxDynamicSharedMemorySize, ATTN_SMEM);

    const dim3 gblk(D_ / 128, M_ / 128);  // (6, 128)

    gemm_kernel<1><<<gblk, 256>>>(X, Wq, bq, qp);
    gemm_kernel<1><<<gblk, 256>>>(X, Wk, bk, kp);
    gemm_kernel<1><<<gblk, 256>>>(X, Wv, bv, vp);

    attn_kernel<<<dim3(N_ / 64, H_, B_), 256, ATTN_SMEM>>>(qp, kp, vp, aop);

    gemm_kernel<0><<<gblk, 256>>>(aop, Wo, bo, out);
}

// round 2
// speedup vs baseline: 2.5377x; 2.5377x over previous
#include <cuda_runtime.h>
#include <stdint.h>
#include <math.h>

#define B_  16
#define N_  1024
#define D_  768
#define H_  12
#define HD_ 64
#define M_  (B_ * N_)   // 16384
#define SCALE_ 0.03608439182435161f  // 1/sqrt(768)

// Scratch (device globals -- no allocation in kernel_launch)
__device__ float g_q[B_ * H_ * N_ * HD_];
__device__ float g_k[B_ * H_ * N_ * HD_];
__device__ float g_v[B_ * H_ * N_ * HD_];
__device__ float g_ao[M_ * D_];

__device__ __forceinline__ uint32_t f2tf(float f) {
    uint32_t u;
    asm("cvt.rna.tf32.f32 %0, %1;" : "=r"(u) : "f"(f));
    return u;
}

__device__ __forceinline__ void mma8(float c[4], const uint32_t a[4], const uint32_t b[2]) {
    asm volatile(
        "mma.sync.aligned.m16n8k8.row.col.f32.tf32.tf32.f32 "
        "{%0,%1,%2,%3}, {%4,%5,%6,%7}, {%8,%9}, {%0,%1,%2,%3};"
        : "+f"(c[0]), "+f"(c[1]), "+f"(c[2]), "+f"(c[3])
        : "r"(a[0]), "r"(a[1]), "r"(a[2]), "r"(a[3]),
          "r"(b[0]), "r"(b[1]));
}

// ---------------------------------------------------------------------------
// TF32 tensor-core GEMM: C = X @ W + bias
//   X: [M_, D_] row-major, W: [D_, D_] row-major
//   MODE 0: out[m*D_ + n]   MODE 1: scatter to [B,H,N,hd]
// CTA tile 128x128x32, 8 warps (2x4), warp tile 64x32 (4x4 m16n8k8 tiles).
// ---------------------------------------------------------------------------
#define SA 132

template <int MODE>
__global__ __launch_bounds__(256)
void gemm_tc(const float* __restrict__ X, const float* __restrict__ W,
             const float* __restrict__ bias, float* __restrict__ out)
{
    __shared__ uint32_t As[32 * SA];   // k-major: As[k][m]
    __shared__ uint32_t Bs[32 * SA];   // k-major: Bs[k][n]

    const int tid  = threadIdx.x;
    const int lane = tid & 31;
    const int wid  = tid >> 5;
    const int wm   = wid >> 2;   // 0..1
    const int wn   = wid & 3;    // 0..3
    const int m0   = blockIdx.y * 128;
    const int n0   = blockIdx.x * 128;

    float acc[4][4][4];
#pragma unroll
    for (int i = 0; i < 4; i++)
#pragma unroll
        for (int j = 0; j < 4; j++)
#pragma unroll
            for (int r = 0; r < 4; r++) acc[i][j][r] = 0.f;

    // A loads: thread -> (row = tid/8 + 32p, kcols = (tid%8)*4 .. +3)
    const int ar = tid >> 3;
    const int ak = (tid & 7) << 2;
    // B loads: thread -> (krow = tid/32 + 8p, ncols = (tid%32)*4 .. +3)
    const int br = tid >> 5;
    const int bn = (tid & 31) << 2;

    const float* Xp = X + (size_t)(m0 + ar) * D_ + ak;
    const float* Wp = W + (size_t)br * D_ + n0 + bn;

    for (int k0 = 0; k0 < D_; k0 += 32) {
        __syncthreads();
#pragma unroll
        for (int p = 0; p < 4; p++) {
            float4 v = *(const float4*)(Xp + k0 + (size_t)p * 32 * D_);
            uint32_t* dst = &As[ak * SA + ar + p * 32];
            dst[0 * SA] = f2tf(v.x);
            dst[1 * SA] = f2tf(v.y);
            dst[2 * SA] = f2tf(v.z);
            dst[3 * SA] = f2tf(v.w);
        }
#pragma unroll
        for (int p = 0; p < 4; p++) {
            float4 v = *(const float4*)(Wp + (size_t)(k0 + p * 8) * D_);
            uint32_t* dst = &Bs[(br + p * 8) * SA + bn];
            dst[0] = f2tf(v.x);
            dst[1] = f2tf(v.y);
            dst[2] = f2tf(v.z);
            dst[3] = f2tf(v.w);
        }
        __syncthreads();

#pragma unroll
        for (int kk = 0; kk < 4; kk++) {
            const int kb = kk * 8 + (lane & 3);
            const int mr = wm * 64 + (lane >> 2);
            uint32_t a[4][4];
#pragma unroll
            for (int i = 0; i < 4; i++) {
                a[i][0] = As[kb * SA + mr + i * 16];
                a[i][1] = As[kb * SA + mr + i * 16 + 8];
                a[i][2] = As[(kb + 4) * SA + mr + i * 16];
                a[i][3] = As[(kb + 4) * SA + mr + i * 16 + 8];
            }
            const int ncb = wn * 32 + (lane >> 2);
            uint32_t b[4][2];
#pragma unroll
            for (int j = 0; j < 4; j++) {
                b[j][0] = Bs[kb * SA + ncb + j * 8];
                b[j][1] = Bs[(kb + 4) * SA + ncb + j * 8];
            }
#pragma unroll
            for (int i = 0; i < 4; i++)
#pragma unroll
                for (int j = 0; j < 4; j++) mma8(acc[i][j], a[i], b[j]);
        }
    }

    // Epilogue: c0,c1 at (row, col..col+1); c2,c3 at (row+8, col..col+1)
#pragma unroll
    for (int i = 0; i < 4; i++) {
#pragma unroll
        for (int j = 0; j < 4; j++) {
            const int row = m0 + wm * 64 + i * 16 + (lane >> 2);
            const int col = n0 + wn * 32 + j * 8 + 2 * (lane & 3);
            const float2 bv = *(const float2*)(bias + col);
            float2 v0 = make_float2(acc[i][j][0] + bv.x, acc[i][j][1] + bv.y);
            float2 v1 = make_float2(acc[i][j][2] + bv.x, acc[i][j][3] + bv.y);
            if (MODE == 0) {
                *(float2*)(out + (size_t)row * D_ + col)       = v0;
                *(float2*)(out + (size_t)(row + 8) * D_ + col) = v1;
            } else {
                const int h = col >> 6;
                const int d = col & 63;
                const int b = row >> 10;
                const int r = row & 1023;
                float* base = out + (((size_t)b * H_ + h) * N_) * HD_ + d;
                *(float2*)(base + (size_t)r * HD_)       = v0;
                *(float2*)(base + (size_t)(r + 8) * HD_) = v1;
            }
        }
    }
}

// ---------------------------------------------------------------------------
// Tensor-core flash attention: CTA per (b, h, 64-row q tile). 4 warps.
// Warp w owns q rows [16w, 16w+16). S and PV via m16n8k8 tf32 mma.
// Online softmax on C fragments (quad shuffles). P reuses the K smem buffer.
// ---------------------------------------------------------------------------
#define AS 68
#define ATTN_SMEM (3 * 64 * AS * 4)

__global__ __launch_bounds__(128)
void attn_tc(const float* __restrict__ Q, const float* __restrict__ K,
             const float* __restrict__ V, float* __restrict__ O)
{
    extern __shared__ uint32_t sm[];
    uint32_t* Qs = sm;                 // [64][AS] tf32
    uint32_t* Ks = sm + 64 * AS;       // K tile, later P tile
    uint32_t* Vs = sm + 2 * 64 * AS;   // V tile

    const int tid  = threadIdx.x;
    const int lane = tid & 31;
    const int wid  = tid >> 5;
    const int b    = blockIdx.z;
    const int h    = blockIdx.y;
    const int q0   = blockIdx.x * 64;

    const float* Qb = Q + (((size_t)b * H_ + h) * N_ + q0) * HD_;
    const float* Kb = K + (((size_t)b * H_ + h) * N_) * HD_;
    const float* Vb = V + (((size_t)b * H_ + h) * N_) * HD_;

    const int lr = tid >> 4;          // 0..7
    const int lc = (tid & 15) << 2;   // 0..60

    // Load Q (scale folded in)
#pragma unroll
    for (int p = 0; p < 8; p++) {
        const int row = lr + p * 8;
        float4 v = *(const float4*)(Qb + (size_t)row * HD_ + lc);
        uint32_t* dst = &Qs[row * AS + lc];
        dst[0] = f2tf(v.x * SCALE_);
        dst[1] = f2tf(v.y * SCALE_);
        dst[2] = f2tf(v.z * SCALE_);
        dst[3] = f2tf(v.w * SCALE_);
    }

    float m0s = -1e30f, m1s = -1e30f, l0s = 0.f, l1s = 0.f;
    float oa[8][4];
#pragma unroll
    for (int nt = 0; nt < 8; nt++)
#pragma unroll
        for (int r = 0; r < 4; r++) oa[nt][r] = 0.f;

    const int qr = wid * 16 + (lane >> 2);   // this thread's first q row

    for (int t = 0; t < 16; t++) {
        __syncthreads();   // prior-iter reads of Ks/Vs complete (and Q load)
        const float* Kt = Kb + (size_t)t * 64 * HD_;
        const float* Vt = Vb + (size_t)t * 64 * HD_;
#pragma unroll
        for (int p = 0; p < 8; p++) {
            const int row = lr + p * 8;
            float4 kv = *(const float4*)(Kt + (size_t)row * HD_ + lc);
            float4 vv = *(const float4*)(Vt + (size_t)row * HD_ + lc);
            uint32_t* kd = &Ks[row * AS + lc];
            kd[0] = f2tf(kv.x); kd[1] = f2tf(kv.y);
            kd[2] = f2tf(kv.z); kd[3] = f2tf(kv.w);
            uint32_t* vd = &Vs[row * AS + lc];
            vd[0] = f2tf(vv.x); vd[1] = f2tf(vv.y);
            vd[2] = f2tf(vv.z); vd[3] = f2tf(vv.w);
        }
        __syncthreads();

        // S = Q K^T
        float sa[8][4];
#pragma unroll
        for (int nt = 0; nt < 8; nt++)
#pragma unroll
            for (int r = 0; r < 4; r++) sa[nt][r] = 0.f;

#pragma unroll
        for (int kk = 0; kk < 8; kk++) {
            const int kb = kk * 8 + (lane & 3);
            uint32_t a[4];
            a[0] = Qs[qr * AS + kb];
            a[1] = Qs[(qr + 8) * AS + kb];
            a[2] = Qs[qr * AS + kb + 4];
            a[3] = Qs[(qr + 8) * AS + kb + 4];
#pragma unroll
            for (int nt = 0; nt < 8; nt++) {
                const int krow = nt * 8 + (lane >> 2);
                uint32_t bb[2];
                bb[0] = Ks[krow * AS + kb];
                bb[1] = Ks[krow * AS + kb + 4];
                mma8(sa[nt], a, bb);
            }
        }

        // Online softmax: rows (qr) via c0,c1 and (qr+8) via c2,c3.
        float tm0 = -1e30f, tm1 = -1e30f;
#pragma unroll
        for (int nt = 0; nt < 8; nt++) {
            tm0 = fmaxf(tm0, fmaxf(sa[nt][0], sa[nt][1]));
            tm1 = fmaxf(tm1, fmaxf(sa[nt][2], sa[nt][3]));
        }
        tm0 = fmaxf(tm0, __shfl_xor_sync(0xffffffffu, tm0, 1));
        tm0 = fmaxf(tm0, __shfl_xor_sync(0xffffffffu, tm0, 2));
        tm1 = fmaxf(tm1, __shfl_xor_sync(0xffffffffu, tm1, 1));
        tm1 = fmaxf(tm1, __shfl_xor_sync(0xffffffffu, tm1, 2));

        const float mn0 = fmaxf(m0s, tm0);
        const float mn1 = fmaxf(m1s, tm1);
        const float c0 = __expf(m0s - mn0);
        const float c1 = __expf(m1s - mn1);
        m0s = mn0; m1s = mn1;

        float rs0 = 0.f, rs1 = 0.f;
#pragma unroll
        for (int nt = 0; nt < 8; nt++) {
            sa[nt][0] = __expf(sa[nt][0] - mn0); rs0 += sa[nt][0];
            sa[nt][1] = __expf(sa[nt][1] - mn0); rs0 += sa[nt][1];
            sa[nt][2] = __expf(sa[nt][2] - mn1); rs1 += sa[nt][2];
            sa[nt][3] = __expf(sa[nt][3] - mn1); rs1 += sa[nt][3];
        }
        rs0 += __shfl_xor_sync(0xffffffffu, rs0, 1);
        rs0 += __shfl_xor_sync(0xffffffffu, rs0, 2);
        rs1 += __shfl_xor_sync(0xffffffffu, rs1, 1);
        rs1 += __shfl_xor_sync(0xffffffffu, rs1, 2);

        l0s = l0s * c0 + rs0;
        l1s = l1s * c1 + rs1;
#pragma unroll
        for (int nt = 0; nt < 8; nt++) {
            oa[nt][0] *= c0; oa[nt][1] *= c0;
            oa[nt][2] *= c1; oa[nt][3] *= c1;
        }

        __syncthreads();   // all warps done reading Ks before P overwrites it

        // Write P (tf32) into Ks region: row = q row, col = key
        const int pcol = 2 * (lane & 3);
#pragma unroll
        for (int nt = 0; nt < 8; nt++) {
            Ks[qr * AS + nt * 8 + pcol]           = f2tf(sa[nt][0]);
            Ks[qr * AS + nt * 8 + pcol + 1]       = f2tf(sa[nt][1]);
            Ks[(qr + 8) * AS + nt * 8 + pcol]     = f2tf(sa[nt][2]);
            Ks[(qr + 8) * AS + nt * 8 + pcol + 1] = f2tf(sa[nt][3]);
        }
        __syncwarp();   // warp reads back only its own 16 P rows

        // O += P @ V
#pragma unroll
        for (int kk = 0; kk < 8; kk++) {
            const int kb = kk * 8 + (lane & 3);
            uint32_t a[4];
            a[0] = Ks[qr * AS + kb];
            a[1] = Ks[(qr + 8) * AS + kb];
            a[2] = Ks[qr * AS + kb + 4];
            a[3] = Ks[(qr + 8) * AS + kb + 4];
#pragma unroll
            for (int nt = 0; nt < 8; nt++) {
                uint32_t bb[2];
                bb[0] = Vs[kb * AS + nt * 8 + (lane >> 2)];
                bb[1] = Vs[(kb + 4) * AS + nt * 8 + (lane >> 2)];
                mma8(oa[nt], a, bb);
            }
        }
    }

    // Normalize + write into [M_, D_] scratch
    const float inv0 = 1.f / l0s;
    const float inv1 = 1.f / l1s;
    const int grow = b * N_ + q0 + qr;
    float* Op = O + (size_t)grow * D_ + h * HD_;
#pragma unroll
    for (int nt = 0; nt < 8; nt++) {
        const int cc = nt * 8 + 2 * (lane & 3);
        float2 v0 = make_float2(oa[nt][0] * inv0, oa[nt][1] * inv0);
        float2 v1 = make_float2(oa[nt][2] * inv1, oa[nt][3] * inv1);
        *(float2*)(Op + cc)           = v0;
        *(float2*)(Op + 8 * D_ + cc)  = v1;
    }
}

// ---------------------------------------------------------------------------
extern "C" void kernel_launch(void* const* d_in, const int* in_sizes, int n_in,
                              void* d_out, int out_size)
{
    const float* X  = (const float*)d_in[0];
    const float* Wq = (const float*)d_in[1];
    const float* bq = (const float*)d_in[2];
    const float* Wk = (const float*)d_in[3];
    const float* bk = (const float*)d_in[4];
    const float* Wv = (const float*)d_in[5];
    const float* bv = (const float*)d_in[6];
    const float* Wo = (const float*)d_in[7];
    const float* bo = (const float*)d_in[8];
    float* out = (float*)d_out;

    float *qp, *kp, *vp, *aop;
    cudaGetSymbolAddress((void**)&qp,  g_q);
    cudaGetSymbolAddress((void**)&kp,  g_k);
    cudaGetSymbolAddress((void**)&vp,  g_v);
    cudaGetSymbolAddress((void**)&aop, g_ao);

    cudaFuncSetAttribute(attn_tc,
                         cudaFuncAttributeMaxDynamicSharedMemorySize, ATTN_SMEM);

    const dim3 gblk(D_ / 128, M_ / 128);  // (6, 128)

    gemm_tc<1><<<gblk, 256>>>(X, Wq, bq, qp);
    gemm_tc<1><<<gblk, 256>>>(X, Wk, bk, kp);
    gemm_tc<1><<<gblk, 256>>>(X, Wv, bv, vp);

    attn_tc<<<dim3(N_ / 64, H_, B_), 128, ATTN_SMEM>>>(qp, kp, vp, aop);

    gemm_tc<0><<<gblk, 256>>>(aop, Wo, bo, out);
}

// round 3
// speedup vs baseline: 4.2459x; 1.6731x over previous
#include <cuda_runtime.h>
#include <stdint.h>
#include <math.h>

#define B_  16
#define N_  1024
#define D_  768
#define H_  12
#define HD_ 64
#define M_  (B_ * N_)            // 16384
#define SCALE_ 0.03608439182435161f  // 1/sqrt(768)
#define NK_ (D_ / 32)            // 24 k-iters

// ---- device scratch (no allocation in kernel_launch) ----
__device__ uint32_t g_xt[M_ * D_];            // X in tf32
__device__ uint32_t g_wqkvt[3 * D_ * D_];     // W_{q,k,v}^T  [n=2304][k=768] tf32
__device__ uint32_t g_wot[D_ * D_];           // W_o^T        [n][k] tf32
__device__ float    g_bqkv[3 * D_];
__device__ uint32_t g_q[B_ * H_ * N_ * HD_];  // [b][h][n][d] tf32 (scale folded)
__device__ uint32_t g_k[B_ * H_ * N_ * HD_];  // [b][h][n][d] tf32
__device__ uint32_t g_v[B_ * H_ * HD_ * N_];  // [b][h][d][n] tf32  (transposed!)
__device__ uint32_t g_ao[M_ * D_];            // attn out, tf32

// ---------------------------------------------------------------------------
__device__ __forceinline__ uint32_t f2tf(float f) {
    uint32_t u;
    asm("cvt.rna.tf32.f32 %0, %1;" : "=r"(u) : "f"(f));
    return u;
}
__device__ __forceinline__ void mma8(float c[4], const uint32_t a[4], const uint32_t b[2]) {
    asm volatile(
        "mma.sync.aligned.m16n8k8.row.col.f32.tf32.tf32.f32 "
        "{%0,%1,%2,%3}, {%4,%5,%6,%7}, {%8,%9}, {%0,%1,%2,%3};"
        : "+f"(c[0]), "+f"(c[1]), "+f"(c[2]), "+f"(c[3])
        : "r"(a[0]), "r"(a[1]), "r"(a[2]), "r"(a[3]), "r"(b[0]), "r"(b[1]));
}
__device__ __forceinline__ uint32_t smaddr(const void* p) {
    return (uint32_t)__cvta_generic_to_shared(p);
}
__device__ __forceinline__ void ldsm4(uint32_t r[4], const void* p) {
    uint32_t a = smaddr(p);
    asm volatile("ldmatrix.sync.aligned.m8n8.x4.shared.b16 {%0,%1,%2,%3}, [%4];"
                 : "=r"(r[0]), "=r"(r[1]), "=r"(r[2]), "=r"(r[3]) : "r"(a));
}
__device__ __forceinline__ void cp16(void* sp, const void* gp) {
    asm volatile("cp.async.cg.shared.global [%0], [%1], 16;"
                 :: "r"(smaddr(sp)), "l"(gp));
}
#define CP_COMMIT asm volatile("cp.async.commit_group;")
#define CP_WAIT0  asm volatile("cp.async.wait_group 0;")
#define CP_WAIT1  asm volatile("cp.async.wait_group 1;")

// ---------------------------------------------------------------------------
// prep kernels (one-time, ~25us total)
// ---------------------------------------------------------------------------
__global__ void prep_x(const float* __restrict__ X, uint32_t* __restrict__ Xt) {
    size_t i = ((size_t)blockIdx.x * 256 + threadIdx.x) * 4;
    float4 v = *(const float4*)(X + i);
    uint4 u = make_uint4(f2tf(v.x), f2tf(v.y), f2tf(v.z), f2tf(v.w));
    *(uint4*)(Xt + i) = u;
}

__global__ void prep_w(const float* __restrict__ Wq, const float* __restrict__ Wk,
                       const float* __restrict__ Wv, const float* __restrict__ Wo,
                       uint32_t* __restrict__ Wqkvt, uint32_t* __restrict__ Wot) {
    __shared__ float t[32][33];
    const int z = blockIdx.z;
    const float* src = (z == 0) ? Wq : (z == 1) ? Wk : (z == 2) ? Wv : Wo;
    uint32_t* dst = (z < 3) ? (Wqkvt + (size_t)z * D_ * D_) : Wot;
    const int x0 = blockIdx.x * 32;   // n
    const int y0 = blockIdx.y * 32;   // k
    const int tx = threadIdx.x, ty = threadIdx.y;
#pragma unroll
    for (int r = 0; r < 4; r++)
        t[ty + 8 * r][tx] = src[(size_t)(y0 + ty + 8 * r) * D_ + x0 + tx];
    __syncthreads();
#pragma unroll
    for (int r = 0; r < 4; r++)
        dst[(size_t)(x0 + ty + 8 * r) * D_ + y0 + tx] = f2tf(t[tx][ty + 8 * r]);
}

__global__ void prep_b(const float* bq, const float* bk, const float* bv, float* bqkv) {
    int i = threadIdx.x;
    bqkv[i] = bq[i]; bqkv[D_ + i] = bk[i]; bqkv[2 * D_ + i] = bv[i];
}

// ---------------------------------------------------------------------------
// GEMM: C = A(tf32 [M][768]) @ Bt(tf32 [N][768])^T + bias
// CTA 128x128x32 double-buffered cp.async; 4 warps (2x2), warp tile 64x64.
// MODE 1: N=2304 fused QKV epilogue -> g_q / g_k / g_v(transposed), tf32 out.
// MODE 0: N=768, f32 out + bias (final projection).
// ---------------------------------------------------------------------------
#define GS 36                      // padded k-stride (36 words = 144B)
#define GEMM_SMEM (4 * 128 * GS * 4)   // 73728 B

template <int MODE>
__global__ __launch_bounds__(128)
void gemm2(const uint32_t* __restrict__ A, const uint32_t* __restrict__ Bt,
           const float* __restrict__ bias, float* __restrict__ outF,
           uint32_t* __restrict__ oq, uint32_t* __restrict__ ok,
           uint32_t* __restrict__ ov)
{
    extern __shared__ uint32_t sg[];
    uint32_t* As = sg;                // [2][128*GS]
    uint32_t* Bs = sg + 2 * 128 * GS;

    const int tid  = threadIdx.x;
    const int lane = tid & 31;
    const int wid  = tid >> 5;
    const int wm   = (wid >> 1) * 64;
    const int wn   = (wid & 1) * 64;
    const int m0   = blockIdx.y * 128;
    const int n0   = blockIdx.x * 128;

    // staging indices: 16 rows x 8 k-chunks, 8 row-passes
    const int lr = tid >> 3;             // 0..15
    const int lk = (tid & 7) << 2;       // 0..28
    const uint32_t* Ap = A  + (size_t)(m0 + lr) * D_ + lk;
    const uint32_t* Bp = Bt + (size_t)(n0 + lr) * D_ + lk;

    float acc[4][8][4];
#pragma unroll
    for (int i = 0; i < 4; i++)
#pragma unroll
        for (int j = 0; j < 8; j++)
#pragma unroll
            for (int r = 0; r < 4; r++) acc[i][j][r] = 0.f;

    // prologue: stage tile 0 into buf 0
    {
        uint32_t* as = As; uint32_t* bs = Bs;
#pragma unroll
        for (int p = 0; p < 8; p++) {
            cp16(&as[(lr + 16 * p) * GS + lk], Ap + (size_t)16 * p * D_);
            cp16(&bs[(lr + 16 * p) * GS + lk], Bp + (size_t)16 * p * D_);
        }
        CP_COMMIT;
    }

    int buf = 0;
    for (int it = 0; it < NK_; it++) {
        __syncthreads();   // everyone done reading buf^1 from iter it-1
        if (it + 1 < NK_) {
            uint32_t* as = As + (buf ^ 1) * 128 * GS;
            uint32_t* bs = Bs + (buf ^ 1) * 128 * GS;
            const uint32_t* ap = Ap + (size_t)(it + 1) * 32;
            const uint32_t* bp = Bp + (size_t)(it + 1) * 32;
#pragma unroll
            for (int p = 0; p < 8; p++) {
                cp16(&as[(lr + 16 * p) * GS + lk], ap + (size_t)16 * p * D_);
                cp16(&bs[(lr + 16 * p) * GS + lk], bp + (size_t)16 * p * D_);
            }
            CP_COMMIT;
            CP_WAIT1;
        } else {
            CP_WAIT0;
        }
        __syncthreads();

        const uint32_t* as = As + buf * 128 * GS;
        const uint32_t* bs = Bs + buf * 128 * GS;
#pragma unroll
        for (int kk = 0; kk < 4; kk++) {
            const int kb = kk * 8;
            uint32_t af[4][4];
#pragma unroll
            for (int i = 0; i < 4; i++)
                ldsm4(af[i], &as[(wm + i * 16 + (lane & 15)) * GS + kb + 4 * (lane >> 4)]);
            uint32_t bf[4][4];
#pragma unroll
            for (int jj = 0; jj < 4; jj++)
                ldsm4(bf[jj], &bs[(wn + jj * 16 + ((lane >> 4) << 3) + (lane & 7)) * GS
                                  + kb + 4 * ((lane >> 3) & 1)]);
#pragma unroll
            for (int i = 0; i < 4; i++)
#pragma unroll
                for (int jj = 0; jj < 4; jj++) {
                    mma8(acc[i][2 * jj],     af[i], &bf[jj][0]);
                    mma8(acc[i][2 * jj + 1], af[i], &bf[jj][2]);
                }
        }
        buf ^= 1;
    }

    // epilogue
    const int mrow0 = m0 + wm + (lane >> 2);
    const int col0  = n0 + wn + 2 * (lane & 3);
#pragma unroll
    for (int i = 0; i < 4; i++) {
#pragma unroll
        for (int j = 0; j < 8; j++) {
            const int row = mrow0 + i * 16;
            const int col = col0 + j * 8;
            const float2 bv = *(const float2*)(bias + col);
            float c0 = acc[i][j][0] + bv.x, c1 = acc[i][j][1] + bv.y;
            float c2 = acc[i][j][2] + bv.x, c3 = acc[i][j][3] + bv.y;
            if (MODE == 0) {
                *(float2*)(outF + (size_t)row * D_ + col)       = make_float2(c0, c1);
                *(float2*)(outF + (size_t)(row + 8) * D_ + col) = make_float2(c2, c3);
            } else {
                const int which = n0 / D_;        // uniform per CTA (128 | 768)
                const int ncol  = col - which * D_;
                const int h = ncol >> 6, d = ncol & 63;
                const int b = row >> 10, r = row & 1023;
                if (which == 0) {
                    uint2 u0 = make_uint2(f2tf(c0 * SCALE_), f2tf(c1 * SCALE_));
                    uint2 u1 = make_uint2(f2tf(c2 * SCALE_), f2tf(c3 * SCALE_));
                    uint32_t* base = oq + ((((size_t)b * H_ + h) * N_) + r) * HD_ + d;
                    *(uint2*)base = u0; *(uint2*)(base + 8 * HD_) = u1;
                } else if (which == 1) {
                    uint2 u0 = make_uint2(f2tf(c0), f2tf(c1));
                    uint2 u1 = make_uint2(f2tf(c2), f2tf(c3));
                    uint32_t* base = ok + ((((size_t)b * H_ + h) * N_) + r) * HD_ + d;
                    *(uint2*)base = u0; *(uint2*)(base + 8 * HD_) = u1;
                } else {
                    // V transposed: [b][h][d][key]
                    uint32_t* base = ov + (((size_t)b * H_ + h) * HD_ + d) * N_ + r;
                    base[0]        = f2tf(c0);
                    base[N_]       = f2tf(c1);   // d+1
                    base[8]        = f2tf(c2);   // r+8
                    base[N_ + 8]   = f2tf(c3);
                }
            }
        }
    }
}

// ---------------------------------------------------------------------------
// Flash attention, tensor cores + ldmatrix. CTA = 128 q rows, 4 warps
// (32 q rows each). K tile 64 keys/iter. All operands pre-converted tf32.
// smem: Qs[128][68], KP[128][68] (K tile rows 0-63, then P tile), Vt[64][68].
// ---------------------------------------------------------------------------
#define AS 68
#define ATTN_SMEM ((128 + 128 + 64) * AS * 4)   // 87040 B

__global__ __launch_bounds__(128)
void attn2(const uint32_t* __restrict__ Q, const uint32_t* __restrict__ K,
           const uint32_t* __restrict__ V, uint32_t* __restrict__ O)
{
    extern __shared__ uint32_t sm[];
    uint32_t* Qs = sm;                  // [128][AS]
    uint32_t* KP = sm + 128 * AS;       // K rows 0-63 -> later P rows 0-127
    uint32_t* Vt = sm + 256 * AS;       // [d=64][AS]

    const int tid  = threadIdx.x;
    const int lane = tid & 31;
    const int wid  = tid >> 5;
    const int b    = blockIdx.z;
    const int h    = blockIdx.y;
    const int q0   = blockIdx.x * 128;

    const uint32_t* Qb = Q + (((size_t)b * H_ + h) * N_ + q0) * HD_;
    const uint32_t* Kb = K + (((size_t)b * H_ + h) * N_) * HD_;
    const uint32_t* Vb = V + (((size_t)b * H_ + h) * HD_) * N_;

    // fill Q tile (128x64) via cp.async
    {
        const int r0 = tid >> 4;             // 0..7
        const int c0 = (tid & 15) << 2;      // 0..60
#pragma unroll
        for (int p = 0; p < 16; p++) {
            const int row = r0 + 8 * p;
            cp16(&Qs[row * AS + c0], Qb + (size_t)row * HD_ + c0);
        }
        CP_COMMIT;
    }

    float oa[2][8][4];
    float ms[2][2], ls[2][2];
#pragma unroll
    for (int i = 0; i < 2; i++) {
        ms[i][0] = ms[i][1] = -1e30f;
        ls[i][0] = ls[i][1] = 0.f;
#pragma unroll
        for (int nt = 0; nt < 8; nt++)
#pragma unroll
            for (int r = 0; r < 4; r++) oa[i][nt][r] = 0.f;
    }

    const int qbase = wid * 32;
    const int fr = tid >> 4;              // fill row helper
    const int fc = (tid & 15) << 2;

    CP_WAIT0; __syncthreads();

    for (int t = 0; t < N_ / 64; t++) {
        // fill K tile [key][d] and Vt tile [d][key]
        const uint32_t* Kt = Kb + (size_t)t * 64 * HD_;
        const uint32_t* Vtg = Vb + (size_t)t * 64;
#pragma unroll
        for (int p = 0; p < 8; p++) {
            const int row = fr + 8 * p;
            cp16(&KP[row * AS + fc], Kt + (size_t)row * HD_ + fc);
            cp16(&Vt[row * AS + fc], Vtg + (size_t)row * N_ + fc);
        }
        CP_COMMIT; CP_WAIT0;
        __syncthreads();

        // ---- S = Q K^T  (per warp: 32 q x 64 keys) ----
        float sa[2][8][4];
#pragma unroll
        for (int i = 0; i < 2; i++)
#pragma unroll
            for (int nt = 0; nt < 8; nt++)
#pragma unroll
                for (int r = 0; r < 4; r++) sa[i][nt][r] = 0.f;

#pragma unroll
        for (int kk = 0; kk < 8; kk++) {
            const int kb = kk * 8;
            uint32_t qa[2][4];
#pragma unroll
            for (int i = 0; i < 2; i++)
                ldsm4(qa[i], &Qs[(qbase + i * 16 + (lane & 15)) * AS + kb + 4 * (lane >> 4)]);
            uint32_t kf[4][4];
#pragma unroll
            for (int jj = 0; jj < 4; jj++)
                ldsm4(kf[jj], &KP[(jj * 16 + ((lane >> 4) << 3) + (lane & 7)) * AS
                                  + kb + 4 * ((lane >> 3) & 1)]);
#pragma unroll
            for (int i = 0; i < 2; i++)
#pragma unroll
                for (int jj = 0; jj < 4; jj++) {
                    mma8(sa[i][2 * jj],     qa[i], &kf[jj][0]);
                    mma8(sa[i][2 * jj + 1], qa[i], &kf[jj][2]);
                }
        }

        // ---- online softmax (rows: i*16 + lane/4 and +8) ----
#pragma unroll
        for (int i = 0; i < 2; i++) {
            float tm0 = -1e30f, tm1 = -1e30f;
#pragma unroll
            for (int nt = 0; nt < 8; nt++) {
                tm0 = fmaxf(tm0, fmaxf(sa[i][nt][0], sa[i][nt][1]));
                tm1 = fmaxf(tm1, fmaxf(sa[i][nt][2], sa[i][nt][3]));
            }
            tm0 = fmaxf(tm0, __shfl_xor_sync(0xffffffffu, tm0, 1));
            tm0 = fmaxf(tm0, __shfl_xor_sync(0xffffffffu, tm0, 2));
            tm1 = fmaxf(tm1, __shfl_xor_sync(0xffffffffu, tm1, 1));
            tm1 = fmaxf(tm1, __shfl_xor_sync(0xffffffffu, tm1, 2));
            const float mn0 = fmaxf(ms[i][0], tm0);
            const float mn1 = fmaxf(ms[i][1], tm1);
            const float c0 = __expf(ms[i][0] - mn0);
            const float c1 = __expf(ms[i][1] - mn1);
            ms[i][0] = mn0; ms[i][1] = mn1;
            float rs0 = 0.f, rs1 = 0.f;
#pragma unroll
            for (int nt = 0; nt < 8; nt++) {
                sa[i][nt][0] = __expf(sa[i][nt][0] - mn0); rs0 += sa[i][nt][0];
                sa[i][nt][1] = __expf(sa[i][nt][1] - mn0); rs0 += sa[i][nt][1];
                sa[i][nt][2] = __expf(sa[i][nt][2] - mn1); rs1 += sa[i][nt][2];
                sa[i][nt][3] = __expf(sa[i][nt][3] - mn1); rs1 += sa[i][nt][3];
            }
            rs0 += __shfl_xor_sync(0xffffffffu, rs0, 1);
            rs0 += __shfl_xor_sync(0xffffffffu, rs0, 2);
            rs1 += __shfl_xor_sync(0xffffffffu, rs1, 1);
            rs1 += __shfl_xor_sync(0xffffffffu, rs1, 2);
            ls[i][0] = ls[i][0] * c0 + rs0;
            ls[i][1] = ls[i][1] * c1 + rs1;
#pragma unroll
            for (int nt = 0; nt < 8; nt++) {
                oa[i][nt][0] *= c0; oa[i][nt][1] *= c0;
                oa[i][nt][2] *= c1; oa[i][nt][3] *= c1;
            }
        }

        __syncthreads();   // all warps done reading K rows of KP

        // ---- write P (tf32) into KP [q 0-127][key] ----
#pragma unroll
        for (int i = 0; i < 2; i++) {
            const int row = qbase + i * 16 + (lane >> 2);
#pragma unroll
            for (int nt = 0; nt < 8; nt++) {
                const int col = nt * 8 + 2 * (lane & 3);
                *(uint2*)&KP[row * AS + col] =
                    make_uint2(f2tf(sa[i][nt][0]), f2tf(sa[i][nt][1]));
                *(uint2*)&KP[(row + 8) * AS + col] =
                    make_uint2(f2tf(sa[i][nt][2]), f2tf(sa[i][nt][3]));
            }
        }
        __syncwarp();      // warp reads back only its own 32 P rows

        // ---- O += P @ V  (B = Vt rows are d_out) ----
#pragma unroll
        for (int kk = 0; kk < 8; kk++) {
            const int kb = kk * 8;
            uint32_t pa[2][4];
#pragma unroll
            for (int i = 0; i < 2; i++)
                ldsm4(pa[i], &KP[(qbase + i * 16 + (lane & 15)) * AS + kb + 4 * (lane >> 4)]);
            uint32_t vf[4][4];
#pragma unroll
            for (int jj = 0; jj < 4; jj++)
                ldsm4(vf[jj], &Vt[(jj * 16 + ((lane >> 4) << 3) + (lane & 7)) * AS
                                  + kb + 4 * ((lane >> 3) & 1)]);
#pragma unroll
            for (int i = 0; i < 2; i++)
#pragma unroll
                for (int jj = 0; jj < 4; jj++) {
                    mma8(oa[i][2 * jj],     pa[i], &vf[jj][0]);
                    mma8(oa[i][2 * jj + 1], pa[i], &vf[jj][2]);
                }
        }
        __syncthreads();   // PV reads done before next-iter K/Vt refill
    }

    // ---- normalize + store tf32 into g_ao [M][768] ----
#pragma unroll
    for (int i = 0; i < 2; i++) {
        const float inv0 = 1.f / ls[i][0];
        const float inv1 = 1.f / ls[i][1];
        const int row = b * N_ + q0 + qbase + i * 16 + (lane >> 2);
        uint32_t* Op = O + (size_t)row * D_ + h * HD_;
#pragma unroll
        for (int nt = 0; nt < 8; nt++) {
            const int cc = nt * 8 + 2 * (lane & 3);
            *(uint2*)(Op + cc) =
                make_uint2(f2tf(oa[i][nt][0] * inv0), f2tf(oa[i][nt][1] * inv0));
            *(uint2*)(Op + (size_t)8 * D_ + cc) =
                make_uint2(f2tf(oa[i][nt][2] * inv1), f2tf(oa[i][nt][3] * inv1));
        }
    }
}

// ---------------------------------------------------------------------------
extern "C" void kernel_launch(void* const* d_in, const int* in_sizes, int n_in,
                              void* d_out, int out_size)
{
    const float* X  = (const float*)d_in[0];
    const float* Wq = (const float*)d_in[1];
    const float* bq = (const float*)d_in[2];
    const float* Wk = (const float*)d_in[3];
    const float* bk = (const float*)d_in[4];
    const float* Wv = (const float*)d_in[5];
    const float* bv = (const float*)d_in[6];
    const float* Wo = (const float*)d_in[7];
    const float* bo = (const float*)d_in[8];
    float* out = (float*)d_out;

    uint32_t *xt, *wqkvt, *wot, *qp, *kp, *vp, *aop;
    float* bqkv;
    cudaGetSymbolAddress((void**)&xt,    g_xt);
    cudaGetSymbolAddress((void**)&wqkvt, g_wqkvt);
    cudaGetSymbolAddress((void**)&wot,   g_wot);
    cudaGetSymbolAddress((void**)&bqkv,  g_bqkv);
    cudaGetSymbolAddress((void**)&qp,    g_q);
    cudaGetSymbolAddress((void**)&kp,    g_k);
    cudaGetSymbolAddress((void**)&vp,    g_v);
    cudaGetSymbolAddress((void**)&aop,   g_ao);

    cudaFuncSetAttribute(gemm2<1>, cudaFuncAttributeMaxDynamicSharedMemorySize, GEMM_SMEM);
    cudaFuncSetAttribute(gemm2<0>, cudaFuncAttributeMaxDynamicSharedMemorySize, GEMM_SMEM);
    cudaFuncSetAttribute(attn2,    cudaFuncAttributeMaxDynamicSharedMemorySize, ATTN_SMEM);

    prep_x<<<M_ * D_ / 1024, 256>>>(X, xt);
    prep_w<<<dim3(24, 24, 4), dim3(32, 8)>>>(Wq, Wk, Wv, Wo, wqkvt, wot);
    prep_b<<<1, D_>>>(bq, bk, bv, bqkv);

    gemm2<1><<<dim3(3 * D_ / 128, M_ / 128), 128, GEMM_SMEM>>>(
        xt, wqkvt, bqkv, nullptr, qp, kp, vp);

    attn2<<<dim3(N_ / 128, H_, B_), 128, ATTN_SMEM>>>(qp, kp, vp, aop);

    gemm2<0><<<dim3(D_ / 128, M_ / 128), 128, GEMM_SMEM>>>(
        aop, wot, bo, out, nullptr, nullptr, nullptr);
}